// round 1
// baseline (speedup 1.0000x reference)
#include <cuda_runtime.h>
#include <stdint.h>

// FSUConv2d: stochastic-computing conv.
// out[b,o] = sum_k ib[b,k]*(t[o,k] > rev8(i1[b,o,k])) + (1-ib[b,k])*(1 - (t[o,k] > rev8(i0[b,o,k]))) + bbit[o]
// where rng[i] = 8-bit bit-reversal of i (Sobol/van-der-Corput), t = w_bin as int in [0,256].
//
// Strategy: bit-sliced comparison. Ballot-transpose 32 idx values into 8 bit
// planes (bit reversal becomes free plane reordering; bits>=8 ignored == %256),
// then an 8-step borrow chain (1 LOP3/bit) computes [rev8(i) < t] for 32
// elements at once. Gate with packed ib bits, count with POPC.

#define NB   2048      // N*H*W
#define OCH  64
#define CKK  288
#define NGRP 9         // 288 / 32

__device__ unsigned g_tp[OCH * NGRP * 9];  // threshold bit planes [o][g][j], j=0..8
__device__ unsigned g_ib[NB * NGRP];       // packed ib bits [b][g], bit m = ib[b, g*32+m]

// ---- precompute threshold bit planes from w_bin -----------------------------
__global__ void prep_tp_kernel(const float* __restrict__ w_bin) {
    int t = blockIdx.x * blockDim.x + threadIdx.x;
    if (t >= OCH * NGRP) return;
    int o = t / NGRP, g = t % NGRP;
    unsigned acc[9];
#pragma unroll
    for (int j = 0; j < 9; ++j) acc[j] = 0u;
    for (int m = 0; m < 32; ++m) {
        int tv = (int)w_bin[o * CKK + g * 32 + m];   // exact integer in [0,256]
#pragma unroll
        for (int j = 0; j < 9; ++j)
            acc[j] |= ((unsigned)(tv >> j) & 1u) << m;
    }
#pragma unroll
    for (int j = 0; j < 9; ++j)
        g_tp[(o * NGRP + g) * 9 + j] = acc[j];
}

// ---- precompute packed unfolded input bits ----------------------------------
__global__ void prep_ib_kernel(const float* __restrict__ x) {
    int t = blockIdx.x * blockDim.x + threadIdx.x;
    if (t >= NB * NGRP) return;
    int b = t / NGRP, g = t % NGRP;
    int n = b >> 8, hw = b & 255, h = hw >> 4, w = hw & 15;
    unsigned word = 0u;
    for (int m = 0; m < 32; ++m) {
        int k  = g * 32 + m;
        int c  = k / 9;
        int r  = k - c * 9;
        int kh = r / 3;
        int kw = r - kh * 3;
        int hh = h + kh - 1, ww = w + kw - 1;
        float v = 0.0f;
        if (hh >= 0 && hh < 16 && ww >= 0 && ww < 16)
            v = x[((n * 32 + c) << 8) + (hh << 4) + ww];
        word |= (v > 0.5f ? 1u : 0u) << m;
    }
    g_ib[b * NGRP + g] = word;
}

// ---- main kernel: one warp per (b, o) pair ----------------------------------
__global__ void __launch_bounds__(256)
fsu_main_kernel(const int* __restrict__ i1g, const int* __restrict__ i0g,
                const float* __restrict__ b_bin, const float* __restrict__ rng,
                const int* __restrict__ brdx, float* __restrict__ out)
{
    __shared__ unsigned s_tp[NGRP * 9];   // planes for this block's o
    __shared__ unsigned s_ib[8][NGRP];    // packed ib for this block's 8 b's

    int o  = blockIdx.x & 63;
    int b0 = (blockIdx.x >> 6) * 8;
    int tid = threadIdx.x;

    if (tid < NGRP * 9)
        s_tp[tid] = g_tp[o * (NGRP * 9) + tid];
    if (tid >= 128 && tid < 128 + 8 * NGRP) {
        int q = tid - 128;
        s_ib[q / NGRP][q % NGRP] = g_ib[(b0 + q / NGRP) * NGRP + (q % NGRP)];
    }
    __syncthreads();

    int wid  = tid >> 5;
    int lane = tid & 31;
    int b    = b0 + wid;

    int base = (b * OCH + o) * CKK + lane;   // max < 2^26, fits int
    const int* p1 = i1g + base;
    const int* p0 = i0g + base;

    unsigned cnt = 0u;
#pragma unroll
    for (int g = 0; g < NGRP; ++g) {
        unsigned v1 = (unsigned)__ldg(p1 + g * 32);
        unsigned v0 = (unsigned)__ldg(p0 + g * 32);

        // transpose to bit planes: a?[j] bit m = bit j of element m's idx
        unsigned a1[8], a0[8];
#pragma unroll
        for (int j = 0; j < 8; ++j) {
            a1[j] = __ballot_sync(0xffffffffu, (v1 & (1u << j)) != 0u);
            a0[j] = __ballot_sync(0xffffffffu, (v0 & (1u << j)) != 0u);
        }

        const unsigned G = s_ib[wid][g];

        // borrow chain for rev8(i) < t : A bit j (significance j) = idx bit (7-j)
        unsigned c1 = 0u, c0 = 0u;
#pragma unroll
        for (int j = 0; j < 8; ++j) {
            unsigned bj  = s_tp[g * 9 + j];
            unsigned na1 = ~a1[7 - j];
            unsigned na0 = ~a0[7 - j];
            c1 = (na1 & bj) | (c1 & (na1 | bj));   // maj(~a, b, c): 1 LOP3
            c0 = (na0 & bj) | (c0 & (na0 | bj));
        }
        unsigned t8 = s_tp[g * 9 + 8];             // t == 256 plane (always-true)

        unsigned m1 = (c1 | t8) & G;               // ib * bit1
        unsigned m0 = ~(c0 | t8 | G);              // (1-ib) * (1-bit0)
        cnt += (unsigned)__popc(m1);
        cnt += (unsigned)__popc(m0);
    }

    if (lane == 0) {
        float bb = (b_bin[o] > rng[brdx[o] & 255]) ? 1.0f : 0.0f;
        int n = b >> 8, hw = b & 255;
        out[(n * OCH + o) * 256 + hw] = (float)cnt + bb;
    }
}

// ---- launch -----------------------------------------------------------------
extern "C" void kernel_launch(void* const* d_in, const int* in_sizes, int n_in,
                              void* d_out, int out_size) {
    const float* x     = (const float*)d_in[0];   // [8,32,16,16]
    const float* w_bin = (const float*)d_in[1];   // [64,288]
    const float* b_bin = (const float*)d_in[2];   // [64]
    const float* rng   = (const float*)d_in[3];   // [256]
    const int*   i1    = (const int*)  d_in[4];   // [2048,64,288]
    const int*   i0    = (const int*)  d_in[5];   // [2048,64,288]
    const int*   brdx  = (const int*)  d_in[6];   // [64]
    float* out = (float*)d_out;                   // [8,64,16,16]

    prep_tp_kernel<<<(OCH * NGRP + 63) / 64, 64>>>(w_bin);
    prep_ib_kernel<<<(NB * NGRP + 255) / 256, 256>>>(x);
    fsu_main_kernel<<<(NB / 8) * OCH, 256>>>(i1, i0, b_bin, rng, brdx, out);
}

// round 2
// speedup vs baseline: 2.9409x; 2.9409x over previous
#include <cuda_runtime.h>

// FSUConv2d via SWAR byte-parallel stochastic-bit counting.
// out[b,o] = sum_k ib[b,k]*(rev8(i1) < t[o,k]) + (1-ib[b,k])*!(rev8(i0) < t[o,k]) + bbit[o]
//
// idx values are int32 in [0,256): pack 4 low bytes per word (PRMT), one BREV
// bit-reverses all 4 bytes, then a per-byte unsigned-compare borrow SWAR
// (1 IADD + 2 LOP3 + 1 LOP3) yields 4 comparisons. Both gated streams combine
// into one POPC. No ballots, no warp-redundant work: 128 element-results per
// warp instruction -> compute sinks below the 302MB HBM streaming floor.

#define NB   2048
#define OCH  64
#define CKK  288
#define NQ   72            // CKK / 4
#define HMASK 0x80808080u

__device__ unsigned g_tw [OCH * NQ];   // clamped thresholds, byte-reversed per quad
__device__ unsigned g_alw[OCH * NQ];   // bit7 flags for t==256 (always-true)
__device__ unsigned g_gw [NB  * NQ];   // ib gate bits at bit7, byte-reversed per quad

// ---- threshold prep ---------------------------------------------------------
__global__ void prep_w(const float* __restrict__ w_bin) {
    int t = blockIdx.x * blockDim.x + threadIdx.x;
    if (t >= OCH * NQ) return;
    int o = t / NQ, q = t % NQ;
    unsigned tw = 0u, alw = 0u;
#pragma unroll
    for (int j = 0; j < 4; ++j) {
        int tv = (int)w_bin[o * CKK + q * 4 + (3 - j)];   // exact int in [0,256]
        unsigned tc = tv > 255 ? 255u : (unsigned)tv;
        tw |= tc << (8 * j);
        if (tv >= 256) alw |= 0x80u << (8 * j);
    }
    g_tw[t] = tw;
    g_alw[t] = alw;
}

// ---- gate prep (unfold x, pack bits at bit7, byte-reversed) -----------------
__global__ void prep_g(const float* __restrict__ x) {
    int t = blockIdx.x * blockDim.x + threadIdx.x;
    if (t >= NB * NQ) return;
    int b = t / NQ, q = t % NQ;
    int n = b >> 8, hw = b & 255, h = hw >> 4, w = hw & 15;
    unsigned gw = 0u;
#pragma unroll
    for (int j = 0; j < 4; ++j) {
        int k  = q * 4 + (3 - j);
        int c  = k / 9;
        int r  = k - c * 9;
        int kh = r / 3;
        int kw = r - kh * 3;
        int hh = h + kh - 1, ww = w + kw - 1;
        float v = 0.0f;
        if ((unsigned)hh < 16u && (unsigned)ww < 16u)
            v = x[((n * 32 + c) << 8) + (hh << 4) + ww];
        if (v > 0.5f) gw |= 0x80u << (8 * j);
    }
    g_gw[t] = gw;
}

// per-byte unsigned a<b at bit7 of each byte (off-bit7 lanes are garbage)
__device__ __forceinline__ unsigned swar_lt(unsigned a, unsigned b) {
    unsigned s = (a | HMASK) - (b & ~HMASK);          // bit7: al >= bl
    return (~a & b) | (~(a ^ b) & ~s);                // one LOP3
}

// ---- main: one warp per (b, o) ----------------------------------------------
__global__ void __launch_bounds__(256)
fsu_main(const int4* __restrict__ i1, const int4* __restrict__ i0,
         const float* __restrict__ b_bin, const float* __restrict__ rng,
         const int* __restrict__ brdx, float* __restrict__ out)
{
    __shared__ unsigned s_tw[NQ], s_alw[NQ], s_gw[8][NQ];

    int o   = blockIdx.x & 63;
    int b0  = (blockIdx.x >> 6) * 8;
    int tid = threadIdx.x;

    if (tid < NQ) {
        s_tw[tid]  = g_tw [o * NQ + tid];
        s_alw[tid] = g_alw[o * NQ + tid];
    }
    for (int i = tid; i < 8 * NQ; i += 256)
        s_gw[i / NQ][i % NQ] = g_gw[(b0 + i / NQ) * NQ + (i % NQ)];
    __syncthreads();

    int wid  = tid >> 5;
    int lane = tid & 31;
    int b    = b0 + wid;

    const int4* p1 = i1 + (b * OCH + o) * NQ;   // 16B-aligned (1152B cells)
    const int4* p0 = i0 + (b * OCH + o) * NQ;

    unsigned cnt = 0u;
#pragma unroll
    for (int it = 0; it < 3; ++it) {
        int q = lane + it * 32;
        if (q < NQ) {                           // iters 0,1 full; iter 2: lanes 0-7
            int4 v1 = __ldg(p1 + q);
            int4 v0 = __ldg(p0 + q);
            // pack 4 low bytes (implements %256 for free)
            unsigned pk1 = __byte_perm(__byte_perm(v1.x, v1.y, 0x0040),
                                       __byte_perm(v1.z, v1.w, 0x0040), 0x5410);
            unsigned pk0 = __byte_perm(__byte_perm(v0.x, v0.y, 0x0040),
                                       __byte_perm(v0.z, v0.w, 0x0040), 0x5410);
            unsigned r1 = __brev(pk1);          // rev8 of all 4 bytes (order flipped)
            unsigned r0 = __brev(pk0);
            unsigned tw  = s_tw[q];
            unsigned alw = s_alw[q];
            unsigned g   = s_gw[wid][q];
            unsigned lt1 = swar_lt(r1, tw);
            unsigned lt0 = swar_lt(r0, tw);
            unsigned f1 = (lt1 | alw) & g;         // ib * bit1        (bit7-clean)
            unsigned f0 = ~(lt0 | alw) & ~g;       // (1-ib)*(1-bit0)  (needs &H)
            cnt += (unsigned)__popc(f1 | (f0 & HMASK));
        }
    }

    cnt = __reduce_add_sync(0xffffffffu, cnt);

    if (lane == 0) {
        float bb = (b_bin[o] > rng[brdx[o] & 255]) ? 1.0f : 0.0f;
        int n = b >> 8, hw = b & 255;
        out[(n * OCH + o) * 256 + hw] = (float)cnt + bb;
    }
}

// ---- launch -----------------------------------------------------------------
extern "C" void kernel_launch(void* const* d_in, const int* in_sizes, int n_in,
                              void* d_out, int out_size) {
    const float* x     = (const float*)d_in[0];   // [8,32,16,16]
    const float* w_bin = (const float*)d_in[1];   // [64,288]
    const float* b_bin = (const float*)d_in[2];   // [64]
    const float* rng   = (const float*)d_in[3];   // [256]
    const int4*  i1    = (const int4*) d_in[4];   // [2048,64,288]
    const int4*  i0    = (const int4*) d_in[5];   // [2048,64,288]
    const int*   brdx  = (const int*)  d_in[6];   // [64]
    float* out = (float*)d_out;                   // [8,64,16,16]

    prep_w<<<(OCH * NQ + 127) / 128, 128>>>(w_bin);
    prep_g<<<(NB * NQ + 255) / 256, 256>>>(x);
    fsu_main<<<(NB / 8) * OCH, 256>>>(i1, i0, b_bin, rng, brdx, out);
}

// round 3
// speedup vs baseline: 3.2626x; 1.1094x over previous
#include <cuda_runtime.h>

// FSUConv2d via SWAR byte-parallel stochastic-bit counting, round 3.
// - One merged prep kernel (thresholds + gates + bias bit).
// - Main kernel: one warp owns 4 consecutive o-cells of one b -> 288 quads
//   = 9 exactly-full warp iterations over 4608B contiguous memory (no ragged
//   tail), per-cell counts split by compile-time lane thresholds.
// - __ldcs streaming loads for the once-read 302MB idx tensors.

#define NB    2048
#define OCH   64
#define CKK   288
#define NQ    72           // CKK / 4
#define HMASK 0x80808080u

__device__ unsigned g_tw [OCH * NQ];   // clamped thresholds, byte-reversed per quad
__device__ unsigned g_alw[OCH * NQ];   // bit7 flags for t==256 (always-true)
__device__ unsigned g_gw [NB  * NQ];   // ib gate bits at bit7, byte-reversed per quad
__device__ float    g_bias[OCH];       // bias bit as float

// ---- merged prep ------------------------------------------------------------
__global__ void prep(const float* __restrict__ w_bin, const float* __restrict__ x,
                     const float* __restrict__ b_bin, const float* __restrict__ rng,
                     const int* __restrict__ brdx)
{
    int t = blockIdx.x * blockDim.x + threadIdx.x;
    if (t >= NB * NQ) return;

    // gate bits (unfold x, bit7 of each byte, byte-reversed within quad)
    {
        int b = t / NQ, q = t % NQ;
        int n = b >> 8, hw = b & 255, h = hw >> 4, w = hw & 15;
        unsigned gw = 0u;
#pragma unroll
        for (int j = 0; j < 4; ++j) {
            int k  = q * 4 + (3 - j);
            int c  = k / 9;
            int r  = k - c * 9;
            int kh = r / 3;
            int kw = r - kh * 3;
            int hh = h + kh - 1, ww = w + kw - 1;
            float v = 0.0f;
            if ((unsigned)hh < 16u && (unsigned)ww < 16u)
                v = x[((n * 32 + c) << 8) + (hh << 4) + ww];
            if (v > 0.5f) gw |= 0x80u << (8 * j);
        }
        g_gw[t] = gw;
    }

    // thresholds
    if (t < OCH * NQ) {
        int o = t / NQ, q = t % NQ;
        unsigned tw = 0u, alw = 0u;
#pragma unroll
        for (int j = 0; j < 4; ++j) {
            int tv = (int)w_bin[o * CKK + q * 4 + (3 - j)];  // exact int in [0,256]
            unsigned tc = tv > 255 ? 255u : (unsigned)tv;
            tw |= tc << (8 * j);
            if (tv >= 256) alw |= 0x80u << (8 * j);
        }
        g_tw[t]  = tw;
        g_alw[t] = alw;
    }

    // bias bit
    if (t < OCH)
        g_bias[t] = (b_bin[t] > rng[brdx[t] & 255]) ? 1.0f : 0.0f;
}

// per-byte unsigned a<b at bit7 of each byte (other bit positions garbage)
__device__ __forceinline__ unsigned swar_lt(unsigned a, unsigned b) {
    unsigned s = (a | HMASK) - (b & ~HMASK);   // bit7 per byte: a_low >= b_low
    return (~a & b) | (~(a ^ b) & ~s);         // single LOP3
}

// ---- main: one warp = (b, o0..o0+3), 9 exactly-full iterations --------------
__global__ void __launch_bounds__(256)
fsu_main(const int4* __restrict__ i1, const int4* __restrict__ i0,
         float* __restrict__ out)
{
    __shared__ unsigned s_tw[32 * NQ], s_alw[32 * NQ], s_gw[NQ];

    int b     = blockIdx.x >> 1;
    int obase = (blockIdx.x & 1) * 32;
    int tid   = threadIdx.x;

    for (int i = tid; i < 32 * NQ; i += 256) {
        s_tw[i]  = g_tw [obase * NQ + i];
        s_alw[i] = g_alw[obase * NQ + i];
    }
    if (tid < NQ) s_gw[tid] = g_gw[b * NQ + tid];
    __syncthreads();

    int w    = tid >> 5;
    int lane = tid & 31;
    int o0   = obase + w * 4;

    const int4* p1 = i1 + (b * OCH + o0) * NQ;   // 4608B contiguous per warp
    const int4* p0 = i0 + (b * OCH + o0) * NQ;

    unsigned cnt[4] = {0u, 0u, 0u, 0u};
#pragma unroll
    for (int it = 0; it < 9; ++it) {
        int g = it * 32 + lane;

        int4 v1 = __ldcs(p1 + g);
        int4 v0 = __ldcs(p0 + g);

        // pack the 4 low bytes (implements %256 for free)
        unsigned pk1 = __byte_perm(__byte_perm(v1.x, v1.y, 0x0040),
                                   __byte_perm(v1.z, v1.w, 0x0040), 0x5410);
        unsigned pk0 = __byte_perm(__byte_perm(v0.x, v0.y, 0x0040),
                                   __byte_perm(v0.z, v0.w, 0x0040), 0x5410);
        unsigned r1 = __brev(pk1);   // rev8 of all 4 bytes at once
        unsigned r0 = __brev(pk0);

        // cell (0..3) this lane's quad belongs to; compile-time per unrolled it
        const int cA  = (it * 32) / 72;
        const int thr = (cA + 1) * 72 - it * 32;
        int cell = (thr >= 32) ? cA : (lane < thr ? cA : cA + 1);
        int q    = g - cell * 72;

        unsigned tw  = s_tw [w * 288 + g];
        unsigned alw = s_alw[w * 288 + g];
        unsigned gt  = s_gw[q];

        unsigned lt1 = swar_lt(r1, tw);
        unsigned lt0 = swar_lt(r0, tw);
        unsigned f1  = (lt1 | alw) & gt;          // ib * bit1           (bit7-clean)
        unsigned nf0 = (lt0 | alw) | gt;          // ~((1-ib)*(1-bit0))
        unsigned p   = (unsigned)__popc(f1 | (~nf0 & HMASK));

        if (thr >= 32) {
            cnt[cA] += p;
        } else {
            if (lane < thr) cnt[cA] += p; else cnt[cA + 1] += p;
        }
    }

#pragma unroll
    for (int c = 0; c < 4; ++c)
        cnt[c] = __reduce_add_sync(0xffffffffu, cnt[c]);

    if (lane == 0) {
        int n = b >> 8, hw = b & 255;
#pragma unroll
        for (int c = 0; c < 4; ++c)
            out[(n * OCH + o0 + c) * 256 + hw] = (float)cnt[c] + g_bias[o0 + c];
    }
}

// ---- launch -----------------------------------------------------------------
extern "C" void kernel_launch(void* const* d_in, const int* in_sizes, int n_in,
                              void* d_out, int out_size) {
    const float* x     = (const float*)d_in[0];   // [8,32,16,16]
    const float* w_bin = (const float*)d_in[1];   // [64,288]
    const float* b_bin = (const float*)d_in[2];   // [64]
    const float* rng   = (const float*)d_in[3];   // [256]
    const int4*  i1    = (const int4*) d_in[4];   // [2048,64,288]
    const int4*  i0    = (const int4*) d_in[5];   // [2048,64,288]
    const int*   brdx  = (const int*)  d_in[6];   // [64]
    float* out = (float*)d_out;                   // [8,64,16,16]

    prep<<<(NB * NQ + 255) / 256, 256>>>(w_bin, x, b_bin, rng, brdx);
    fsu_main<<<NB * 2, 256>>>(i1, i0, out);
}

// round 4
// speedup vs baseline: 3.3558x; 1.0286x over previous
#include <cuda_runtime.h>

// FSUConv2d via SWAR byte-parallel stochastic-bit counting, round 4.
// R3 -> R4: explicit 3-iteration LDG bursts (6x LDG.128 in flight per warp)
// + __launch_bounds__(256,5) to give ptxas the registers for it; tw/alw fused
// into one uint2 smem load. Goal: lift DRAM from 67.7% toward the ~6.9TB/s
// achieved ceiling.

#define NB    2048
#define OCH   64
#define CKK   288
#define NQ    72           // CKK / 4
#define HMASK 0x80808080u

__device__ uint2    g_twal[OCH * NQ];  // .x = clamped thresholds (byte-reversed), .y = t==256 bit7 flags
__device__ unsigned g_gw [NB  * NQ];   // ib gate bits at bit7, byte-reversed per quad
__device__ float    g_bias[OCH];       // bias bit as float

// ---- merged prep ------------------------------------------------------------
__global__ void prep(const float* __restrict__ w_bin, const float* __restrict__ x,
                     const float* __restrict__ b_bin, const float* __restrict__ rng,
                     const int* __restrict__ brdx)
{
    int t = blockIdx.x * blockDim.x + threadIdx.x;
    if (t >= NB * NQ) return;

    // gate bits (unfold x, bit7 of each byte, byte-reversed within quad)
    {
        int b = t / NQ, q = t % NQ;
        int n = b >> 8, hw = b & 255, h = hw >> 4, w = hw & 15;
        unsigned gw = 0u;
#pragma unroll
        for (int j = 0; j < 4; ++j) {
            int k  = q * 4 + (3 - j);
            int c  = k / 9;
            int r  = k - c * 9;
            int kh = r / 3;
            int kw = r - kh * 3;
            int hh = h + kh - 1, ww = w + kw - 1;
            float v = 0.0f;
            if ((unsigned)hh < 16u && (unsigned)ww < 16u)
                v = x[((n * 32 + c) << 8) + (hh << 4) + ww];
            if (v > 0.5f) gw |= 0x80u << (8 * j);
        }
        g_gw[t] = gw;
    }

    // thresholds
    if (t < OCH * NQ) {
        int o = t / NQ, q = t % NQ;
        unsigned tw = 0u, alw = 0u;
#pragma unroll
        for (int j = 0; j < 4; ++j) {
            int tv = (int)w_bin[o * CKK + q * 4 + (3 - j)];  // exact int in [0,256]
            unsigned tc = tv > 255 ? 255u : (unsigned)tv;
            tw |= tc << (8 * j);
            if (tv >= 256) alw |= 0x80u << (8 * j);
        }
        g_twal[t] = make_uint2(tw, alw);
    }

    // bias bit
    if (t < OCH)
        g_bias[t] = (b_bin[t] > rng[brdx[t] & 255]) ? 1.0f : 0.0f;
}

// per-byte unsigned a<b at bit7 of each byte (other bit positions garbage)
__device__ __forceinline__ unsigned swar_lt(unsigned a, unsigned b) {
    unsigned s = (a | HMASK) - (b & ~HMASK);   // bit7 per byte: a_low >= b_low
    return (~a & b) | (~(a ^ b) & ~s);         // single LOP3
}

// ---- main: one warp = (b, o0..o0+3); 9 iters in 3 bursts of 3 ---------------
__global__ void __launch_bounds__(256, 5)
fsu_main(const int4* __restrict__ i1, const int4* __restrict__ i0,
         float* __restrict__ out)
{
    __shared__ uint2    s_twal[32 * NQ];
    __shared__ unsigned s_gw[NQ];

    int b     = blockIdx.x >> 1;
    int obase = (blockIdx.x & 1) * 32;
    int tid   = threadIdx.x;

    for (int i = tid; i < 32 * NQ; i += 256)
        s_twal[i] = g_twal[obase * NQ + i];
    if (tid < NQ) s_gw[tid] = g_gw[b * NQ + tid];
    __syncthreads();

    int w    = tid >> 5;
    int lane = tid & 31;
    int o0   = obase + w * 4;

    const int4* p1 = i1 + (b * OCH + o0) * NQ + lane;  // 4608B contiguous per warp
    const int4* p0 = i0 + (b * OCH + o0) * NQ + lane;

    unsigned cnt[4] = {0u, 0u, 0u, 0u};

#pragma unroll
    for (int s = 0; s < 3; ++s) {
        // burst: 6 LDG.128 back-to-back -> 24 lines outstanding per warp
        int4 a1[3], a0[3];
#pragma unroll
        for (int j = 0; j < 3; ++j) {
            a1[j] = __ldcs(p1 + (s * 3 + j) * 32);
            a0[j] = __ldcs(p0 + (s * 3 + j) * 32);
        }

#pragma unroll
        for (int j = 0; j < 3; ++j) {
            const int it = s * 3 + j;
            const int g  = it * 32;          // + lane at use sites

            unsigned pk1 = __byte_perm(__byte_perm(a1[j].x, a1[j].y, 0x0040),
                                       __byte_perm(a1[j].z, a1[j].w, 0x0040), 0x5410);
            unsigned pk0 = __byte_perm(__byte_perm(a0[j].x, a0[j].y, 0x0040),
                                       __byte_perm(a0[j].z, a0[j].w, 0x0040), 0x5410);
            unsigned r1 = __brev(pk1);       // rev8 of all 4 bytes at once
            unsigned r0 = __brev(pk0);

            // which o-cell (0..3) this lane's quad belongs to (compile-time split)
            const int cA  = g / 72;
            const int thr = (cA + 1) * 72 - g;

            uint2    twal = s_twal[w * 288 + g + lane];
            unsigned gt;
            if (thr >= 32) gt = s_gw[g + lane - cA * 72];
            else           gt = s_gw[(lane < thr) ? (g + lane - cA * 72)
                                                  : (g + lane - (cA + 1) * 72)];

            unsigned lt1 = swar_lt(r1, twal.x);
            unsigned lt0 = swar_lt(r0, twal.x);
            unsigned f1  = (lt1 | twal.y) & gt;     // ib * bit1          (bit7-clean)
            unsigned nf0 = (lt0 | twal.y) | gt;     // ~((1-ib)*(1-bit0))
            unsigned p   = (unsigned)__popc(f1 | (~nf0 & HMASK));

            if (thr >= 32) {
                cnt[cA] += p;
            } else {
                if (lane < thr) cnt[cA] += p; else cnt[cA + 1] += p;
            }
        }
    }

#pragma unroll
    for (int c = 0; c < 4; ++c)
        cnt[c] = __reduce_add_sync(0xffffffffu, cnt[c]);

    if (lane == 0) {
        int n = b >> 8, hw = b & 255;
#pragma unroll
        for (int c = 0; c < 4; ++c)
            out[(n * OCH + o0 + c) * 256 + hw] = (float)cnt[c] + g_bias[o0 + c];
    }
}

// ---- launch -----------------------------------------------------------------
extern "C" void kernel_launch(void* const* d_in, const int* in_sizes, int n_in,
                              void* d_out, int out_size) {
    const float* x     = (const float*)d_in[0];   // [8,32,16,16]
    const float* w_bin = (const float*)d_in[1];   // [64,288]
    const float* b_bin = (const float*)d_in[2];   // [64]
    const float* rng   = (const float*)d_in[3];   // [256]
    const int4*  i1    = (const int4*) d_in[4];   // [2048,64,288]
    const int4*  i0    = (const int4*) d_in[5];   // [2048,64,288]
    const int*   brdx  = (const int*)  d_in[6];   // [64]
    float* out = (float*)d_out;                   // [8,64,16,16]

    prep<<<(NB * NQ + 255) / 256, 256>>>(w_bin, x, b_bin, rng, brdx);
    fsu_main<<<NB * 2, 256>>>(i1, i0, out);
}

// round 5
// speedup vs baseline: 3.4831x; 1.0379x over previous
#include <cuda_runtime.h>

// FSUConv2d via SWAR byte-parallel stochastic-bit counting, round 5.
// R4 -> R5: persistent grid-stride blocks (740 = 148 SM x 5 CTA). Each block
// fixes its o-half, loads the 18KB threshold table into smem ONCE, then
// streams all its (b) work units barrier-free. Gate words read straight from
// L2 via __ldg. Removes per-wave table reload windows that were starving DRAM.

#define NB    2048
#define OCH   64
#define CKK   288
#define NQ    72           // CKK / 4
#define HMASK 0x80808080u
#define GRID  740          // 148 SMs x 5 resident CTAs (even: o-half invariant)

__device__ uint2    g_twal[OCH * NQ];  // .x = clamped thresholds (byte-rev), .y = t==256 bit7 flags
__device__ unsigned g_gw [NB  * NQ];   // ib gate bits at bit7, byte-reversed per quad
__device__ float    g_bias[OCH];       // bias bit as float

// ---- merged prep ------------------------------------------------------------
__global__ void prep(const float* __restrict__ w_bin, const float* __restrict__ x,
                     const float* __restrict__ b_bin, const float* __restrict__ rng,
                     const int* __restrict__ brdx)
{
    int t = blockIdx.x * blockDim.x + threadIdx.x;
    if (t >= NB * NQ) return;

    // gate bits (unfold x, bit7 of each byte, byte-reversed within quad)
    {
        int b = t / NQ, q = t % NQ;
        int n = b >> 8, hw = b & 255, h = hw >> 4, w = hw & 15;
        unsigned gw = 0u;
#pragma unroll
        for (int j = 0; j < 4; ++j) {
            int k  = q * 4 + (3 - j);
            int c  = k / 9;
            int r  = k - c * 9;
            int kh = r / 3;
            int kw = r - kh * 3;
            int hh = h + kh - 1, ww = w + kw - 1;
            float v = 0.0f;
            if ((unsigned)hh < 16u && (unsigned)ww < 16u)
                v = x[((n * 32 + c) << 8) + (hh << 4) + ww];
            if (v > 0.5f) gw |= 0x80u << (8 * j);
        }
        g_gw[t] = gw;
    }

    // thresholds
    if (t < OCH * NQ) {
        int o = t / NQ, q = t % NQ;
        unsigned tw = 0u, alw = 0u;
#pragma unroll
        for (int j = 0; j < 4; ++j) {
            int tv = (int)w_bin[o * CKK + q * 4 + (3 - j)];  // exact int in [0,256]
            unsigned tc = tv > 255 ? 255u : (unsigned)tv;
            tw |= tc << (8 * j);
            if (tv >= 256) alw |= 0x80u << (8 * j);
        }
        g_twal[t] = make_uint2(tw, alw);
    }

    // bias bit
    if (t < OCH)
        g_bias[t] = (b_bin[t] > rng[brdx[t] & 255]) ? 1.0f : 0.0f;
}

// per-byte unsigned a<b at bit7 of each byte (other bit positions garbage)
__device__ __forceinline__ unsigned swar_lt(unsigned a, unsigned b) {
    unsigned s = (a | HMASK) - (b & ~HMASK);   // bit7 per byte: a_low >= b_low
    return (~a & b) | (~(a ^ b) & ~s);         // single LOP3
}

// ---- main: persistent; one warp handles (b, o0..o0+3) per unit --------------
__global__ void __launch_bounds__(256, 5)
fsu_main(const int4* __restrict__ i1, const int4* __restrict__ i0,
         float* __restrict__ out)
{
    __shared__ uint2 s_twal[32 * NQ];     // thresholds for this block's o-half

    int bid   = blockIdx.x;
    int obase = (bid & 1) * 32;           // invariant: stride GRID is even
    int tid   = threadIdx.x;

    for (int i = tid; i < 32 * NQ; i += 256)
        s_twal[i] = g_twal[obase * NQ + i];
    __syncthreads();                      // once per block, ever

    int w    = tid >> 5;
    int lane = tid & 31;
    int o0   = obase + w * 4;

    for (int u = bid; u < NB * 2; u += GRID) {
        int b = u >> 1;

        const int4* p1 = i1 + (b * OCH + o0) * NQ + lane;  // 4608B contiguous/warp
        const int4* p0 = i0 + (b * OCH + o0) * NQ + lane;
        const unsigned* gwrow = g_gw + b * NQ;             // L2-resident (589KB)

        unsigned cnt[4] = {0u, 0u, 0u, 0u};

#pragma unroll
        for (int s = 0; s < 3; ++s) {
            // burst: 6 LDG.128 back-to-back
            int4 a1[3], a0[3];
#pragma unroll
            for (int j = 0; j < 3; ++j) {
                a1[j] = __ldcs(p1 + (s * 3 + j) * 32);
                a0[j] = __ldcs(p0 + (s * 3 + j) * 32);
            }

#pragma unroll
            for (int j = 0; j < 3; ++j) {
                const int it = s * 3 + j;
                const int g  = it * 32;

                unsigned pk1 = __byte_perm(__byte_perm(a1[j].x, a1[j].y, 0x0040),
                                           __byte_perm(a1[j].z, a1[j].w, 0x0040), 0x5410);
                unsigned pk0 = __byte_perm(__byte_perm(a0[j].x, a0[j].y, 0x0040),
                                           __byte_perm(a0[j].z, a0[j].w, 0x0040), 0x5410);
                unsigned r1 = __brev(pk1);     // rev8 of all 4 bytes at once
                unsigned r0 = __brev(pk0);

                // o-cell (0..3) for this lane's quad (compile-time split points)
                const int cA  = g / 72;
                const int thr = (cA + 1) * 72 - g;
                const int qb  = g - cA * 72;

                int q;
                if (thr >= 32) q = qb + lane;
                else           q = (lane < thr) ? (qb + lane) : (qb + lane - 72);
                unsigned gt = __ldg(gwrow + q);

                uint2 twal = s_twal[w * 288 + g + lane];

                unsigned lt1 = swar_lt(r1, twal.x);
                unsigned lt0 = swar_lt(r0, twal.x);
                unsigned f1  = (lt1 | twal.y) & gt;     // ib * bit1         (bit7-clean)
                unsigned nf0 = (lt0 | twal.y) | gt;     // ~((1-ib)*(1-bit0))
                unsigned p   = (unsigned)__popc(f1 | (~nf0 & HMASK));

                if (thr >= 32) {
                    cnt[cA] += p;
                } else {
                    if (lane < thr) cnt[cA] += p; else cnt[cA + 1] += p;
                }
            }
        }

#pragma unroll
        for (int c = 0; c < 4; ++c)
            cnt[c] = __reduce_add_sync(0xffffffffu, cnt[c]);

        if (lane == 0) {
            int n = b >> 8, hw = b & 255;
#pragma unroll
            for (int c = 0; c < 4; ++c)
                out[(n * OCH + o0 + c) * 256 + hw] = (float)cnt[c] + g_bias[o0 + c];
        }
    }
}

// ---- launch -----------------------------------------------------------------
extern "C" void kernel_launch(void* const* d_in, const int* in_sizes, int n_in,
                              void* d_out, int out_size) {
    const float* x     = (const float*)d_in[0];   // [8,32,16,16]
    const float* w_bin = (const float*)d_in[1];   // [64,288]
    const float* b_bin = (const float*)d_in[2];   // [64]
    const float* rng   = (const float*)d_in[3];   // [256]
    const int4*  i1    = (const int4*) d_in[4];   // [2048,64,288]
    const int4*  i0    = (const int4*) d_in[5];   // [2048,64,288]
    const int*   brdx  = (const int*)  d_in[6];   // [64]
    float* out = (float*)d_out;                   // [8,64,16,16]

    prep<<<(NB * NQ + 255) / 256, 256>>>(w_bin, x, b_bin, rng, brdx);
    fsu_main<<<GRID, 256>>>(i1, i0, out);
}

// round 6
// speedup vs baseline: 3.6138x; 1.0375x over previous
#include <cuda_runtime.h>

// FSUConv2d via SWAR byte-parallel stochastic-bit counting, round 6.
// R5 -> R6: schedule re-quantization. GRID=592 (148 SM x 4 CTA, SM-uniform),
// warp-level unit pool: 16384 units per o-half over 2368 warps = 7-vs-6
// units/warp (1.2% quantization) instead of 6-vs-5 over 2960 (8%). Warps roam
// over o-quads within their block's resident threshold half.

#define NB    2048
#define OCH   64
#define CKK   288
#define NQ    72           // CKK / 4
#define HMASK 0x80808080u
#define GRID  592          // 148 SMs x 4 resident CTAs (even: o-half invariant)
#define WHALF (GRID / 2 * 8)   // 2368 warps per o-half
#define UNITS (NB * 8)         // 16384 units per o-half (b x o-quad)

__device__ uint2    g_twal[OCH * NQ];  // .x = clamped thresholds (byte-rev), .y = t==256 bit7 flags
__device__ unsigned g_gw [NB  * NQ];   // ib gate bits at bit7, byte-reversed per quad
__device__ float    g_bias[OCH];       // bias bit as float

// ---- merged prep ------------------------------------------------------------
__global__ void prep(const float* __restrict__ w_bin, const float* __restrict__ x,
                     const float* __restrict__ b_bin, const float* __restrict__ rng,
                     const int* __restrict__ brdx)
{
    int t = blockIdx.x * blockDim.x + threadIdx.x;
    if (t >= NB * NQ) return;

    // gate bits (unfold x, bit7 of each byte, byte-reversed within quad)
    {
        int b = t / NQ, q = t % NQ;
        int n = b >> 8, hw = b & 255, h = hw >> 4, w = hw & 15;
        unsigned gw = 0u;
#pragma unroll
        for (int j = 0; j < 4; ++j) {
            int k  = q * 4 + (3 - j);
            int c  = k / 9;
            int r  = k - c * 9;
            int kh = r / 3;
            int kw = r - kh * 3;
            int hh = h + kh - 1, ww = w + kw - 1;
            float v = 0.0f;
            if ((unsigned)hh < 16u && (unsigned)ww < 16u)
                v = x[((n * 32 + c) << 8) + (hh << 4) + ww];
            if (v > 0.5f) gw |= 0x80u << (8 * j);
        }
        g_gw[t] = gw;
    }

    // thresholds
    if (t < OCH * NQ) {
        int o = t / NQ, q = t % NQ;
        unsigned tw = 0u, alw = 0u;
#pragma unroll
        for (int j = 0; j < 4; ++j) {
            int tv = (int)w_bin[o * CKK + q * 4 + (3 - j)];  // exact int in [0,256]
            unsigned tc = tv > 255 ? 255u : (unsigned)tv;
            tw |= tc << (8 * j);
            if (tv >= 256) alw |= 0x80u << (8 * j);
        }
        g_twal[t] = make_uint2(tw, alw);
    }

    // bias bit
    if (t < OCH)
        g_bias[t] = (b_bin[t] > rng[brdx[t] & 255]) ? 1.0f : 0.0f;
}

// per-byte unsigned a<b at bit7 of each byte (other bit positions garbage)
__device__ __forceinline__ unsigned swar_lt(unsigned a, unsigned b) {
    unsigned s = (a | HMASK) - (b & ~HMASK);   // bit7 per byte: a_low >= b_low
    return (~a & b) | (~(a ^ b) & ~s);         // single LOP3
}

// ---- main: persistent; warp-level units (b, o-quad) within block's o-half ---
__global__ void __launch_bounds__(256, 4)
fsu_main(const int4* __restrict__ i1, const int4* __restrict__ i0,
         float* __restrict__ out)
{
    __shared__ uint2 s_twal[32 * NQ];     // thresholds for this block's o-half

    int bid   = blockIdx.x;
    int obase = (bid & 1) * 32;           // invariant under even GRID stride
    int tid   = threadIdx.x;

    for (int i = tid; i < 32 * NQ; i += 256)
        s_twal[i] = g_twal[obase * NQ + i];
    __syncthreads();                      // once per block, ever

    int w    = tid >> 5;
    int lane = tid & 31;
    int hwid = (bid >> 1) * 8 + w;        // warp id within this o-half pool

    for (int u = hwid; u < UNITS; u += WHALF) {
        int b  = u >> 3;
        int qw = u & 7;                   // o-quad within half
        int o0 = obase + qw * 4;

        const int4* p1 = i1 + (b * OCH + o0) * NQ + lane;  // 4608B contiguous/warp
        const int4* p0 = i0 + (b * OCH + o0) * NQ + lane;
        const unsigned* gwrow = g_gw + b * NQ;             // L2-resident (589KB)

        unsigned cnt[4] = {0u, 0u, 0u, 0u};

#pragma unroll
        for (int s = 0; s < 3; ++s) {
            // burst: 6 LDG.128 back-to-back
            int4 a1[3], a0[3];
#pragma unroll
            for (int j = 0; j < 3; ++j) {
                a1[j] = __ldcs(p1 + (s * 3 + j) * 32);
                a0[j] = __ldcs(p0 + (s * 3 + j) * 32);
            }

#pragma unroll
            for (int j = 0; j < 3; ++j) {
                const int it = s * 3 + j;
                const int g  = it * 32;

                unsigned pk1 = __byte_perm(__byte_perm(a1[j].x, a1[j].y, 0x0040),
                                           __byte_perm(a1[j].z, a1[j].w, 0x0040), 0x5410);
                unsigned pk0 = __byte_perm(__byte_perm(a0[j].x, a0[j].y, 0x0040),
                                           __byte_perm(a0[j].z, a0[j].w, 0x0040), 0x5410);
                unsigned r1 = __brev(pk1);     // rev8 of all 4 bytes at once
                unsigned r0 = __brev(pk0);

                // o-cell (0..3) for this lane's quad (compile-time split points)
                const int cA  = g / 72;
                const int thr = (cA + 1) * 72 - g;
                const int qb  = g - cA * 72;

                int q;
                if (thr >= 32) q = qb + lane;
                else           q = (lane < thr) ? (qb + lane) : (qb + lane - 72);
                unsigned gt = __ldg(gwrow + q);

                uint2 twal = s_twal[qw * 288 + g + lane];

                unsigned lt1 = swar_lt(r1, twal.x);
                unsigned lt0 = swar_lt(r0, twal.x);
                unsigned f1  = (lt1 | twal.y) & gt;     // ib * bit1         (bit7-clean)
                unsigned nf0 = (lt0 | twal.y) | gt;     // ~((1-ib)*(1-bit0))
                unsigned p   = (unsigned)__popc(f1 | (~nf0 & HMASK));

                if (thr >= 32) {
                    cnt[cA] += p;
                } else {
                    if (lane < thr) cnt[cA] += p; else cnt[cA + 1] += p;
                }
            }
        }

#pragma unroll
        for (int c = 0; c < 4; ++c)
            cnt[c] = __reduce_add_sync(0xffffffffu, cnt[c]);

        if (lane == 0) {
            int n = b >> 8, hw = b & 255;
#pragma unroll
            for (int c = 0; c < 4; ++c)
                out[(n * OCH + o0 + c) * 256 + hw] = (float)cnt[c] + g_bias[o0 + c];
        }
    }
}

// ---- launch -----------------------------------------------------------------
extern "C" void kernel_launch(void* const* d_in, const int* in_sizes, int n_in,
                              void* d_out, int out_size) {
    const float* x     = (const float*)d_in[0];   // [8,32,16,16]
    const float* w_bin = (const float*)d_in[1];   // [64,288]
    const float* b_bin = (const float*)d_in[2];   // [64]
    const float* rng   = (const float*)d_in[3];   // [256]
    const int4*  i1    = (const int4*) d_in[4];   // [2048,64,288]
    const int4*  i0    = (const int4*) d_in[5];   // [2048,64,288]
    const int*   brdx  = (const int*)  d_in[6];   // [64]
    float* out = (float*)d_out;                   // [8,64,16,16]

    prep<<<(NB * NQ + 255) / 256, 256>>>(w_bin, x, b_bin, rng, brdx);
    fsu_main<<<GRID, 256>>>(i1, i0, out);
}

// round 7
// speedup vs baseline: 3.6361x; 1.0062x over previous
#include <cuda_runtime.h>

// FSUConv2d via SWAR byte-parallel stochastic-bit counting, round 7.
// R6 -> R7: PDL overlap. Main builds its threshold smem table straight from
// w_bin (no prep dependency), launches programmatically-overlapped with the
// gate-word prep kernel, and griddepcontrol.wait's only before its first
// g_gw read. Counter packing: 2x REDUX instead of 4x.

#define NB    2048
#define OCH   64
#define CKK   288
#define NQ    72           // CKK / 4
#define HMASK 0x80808080u
#define GRID  592          // 148 SMs x 4 resident CTAs (even: o-half invariant)
#define WHALF (GRID / 2 * 8)   // 2368 warps per o-half
#define UNITS (NB * 8)         // 16384 units per o-half (b x o-quad)

__device__ unsigned g_gw [NB * NQ];    // ib gate bits at bit7, byte-reversed per quad
__device__ float    g_bias[OCH];       // bias bit as float

// ---- prep: gate words + bias only -------------------------------------------
__global__ void prep(const float* __restrict__ x,
                     const float* __restrict__ b_bin, const float* __restrict__ rng,
                     const int* __restrict__ brdx)
{
    int t = blockIdx.x * blockDim.x + threadIdx.x;
    if (t < NB * NQ) {
        int b = t / NQ, q = t % NQ;
        int n = b >> 8, hw = b & 255, h = hw >> 4, w = hw & 15;
        unsigned gw = 0u;
#pragma unroll
        for (int j = 0; j < 4; ++j) {
            int k  = q * 4 + (3 - j);
            int c  = k / 9;
            int r  = k - c * 9;
            int kh = r / 3;
            int kw = r - kh * 3;
            int hh = h + kh - 1, ww = w + kw - 1;
            float v = 0.0f;
            if ((unsigned)hh < 16u && (unsigned)ww < 16u)
                v = x[((n * 32 + c) << 8) + (hh << 4) + ww];
            if (v > 0.5f) gw |= 0x80u << (8 * j);
        }
        g_gw[t] = gw;
        if (t < OCH)
            g_bias[t] = (b_bin[t] > rng[brdx[t] & 255]) ? 1.0f : 0.0f;
    }
    // allow the dependent (main) grid to start launching
    asm volatile("griddepcontrol.launch_dependents;");
}

// per-byte unsigned a<b at bit7 of each byte (other bit positions garbage)
__device__ __forceinline__ unsigned swar_lt(unsigned a, unsigned b) {
    unsigned s = (a | HMASK) - (b & ~HMASK);   // bit7 per byte: a_low >= b_low
    return (~a & b) | (~(a ^ b) & ~s);         // single LOP3
}

// ---- main: persistent; warp-level units (b, o-quad) within block's o-half ---
__global__ void __launch_bounds__(256, 4)
fsu_main(const int4* __restrict__ i1, const int4* __restrict__ i0,
         const float* __restrict__ w_bin, float* __restrict__ out)
{
    __shared__ uint2 s_twal[32 * NQ];     // thresholds for this block's o-half

    int bid   = blockIdx.x;
    int obase = (bid & 1) * 32;           // invariant under even GRID stride
    int tid   = threadIdx.x;

    // Build threshold table straight from w_bin (independent of prep -> runs
    // concurrently with prep under PDL).
#pragma unroll
    for (int j = 0; j < (32 * NQ) / 256; ++j) {
        int i = tid + j * 256;
        int o = obase + i / NQ, q = i - (i / NQ) * NQ;
        const float4 wv = *(const float4*)(w_bin + o * CKK + q * 4);
        float tvf[4] = {wv.x, wv.y, wv.z, wv.w};
        unsigned tw = 0u, alw = 0u;
#pragma unroll
        for (int jj = 0; jj < 4; ++jj) {
            int tv = (int)tvf[3 - jj];                   // exact int in [0,256]
            unsigned tc = tv > 255 ? 255u : (unsigned)tv;
            tw |= tc << (8 * jj);
            if (tv >= 256) alw |= 0x80u << (8 * jj);
        }
        s_twal[i] = make_uint2(tw, alw);
    }
    __syncthreads();

    // wait for prep's g_gw / g_bias to be visible
    asm volatile("griddepcontrol.wait;");

    int w    = tid >> 5;
    int lane = tid & 31;
    int hwid = (bid >> 1) * 8 + w;        // warp id within this o-half pool

    for (int u = hwid; u < UNITS; u += WHALF) {
        int b  = u >> 3;
        int qw = u & 7;                   // o-quad within half
        int o0 = obase + qw * 4;

        const int4* p1 = i1 + (b * OCH + o0) * NQ + lane;  // 4608B contiguous/warp
        const int4* p0 = i0 + (b * OCH + o0) * NQ + lane;
        const unsigned* gwrow = g_gw + b * NQ;             // L2-resident (589KB)

        unsigned c01 = 0u, c23 = 0u;      // packed counters: lo16 = even cell

#pragma unroll
        for (int s = 0; s < 3; ++s) {
            // burst: 6 LDG.128 back-to-back
            int4 a1[3], a0[3];
#pragma unroll
            for (int j = 0; j < 3; ++j) {
                a1[j] = __ldcs(p1 + (s * 3 + j) * 32);
                a0[j] = __ldcs(p0 + (s * 3 + j) * 32);
            }

#pragma unroll
            for (int j = 0; j < 3; ++j) {
                const int it = s * 3 + j;
                const int g  = it * 32;

                unsigned pk1 = __byte_perm(__byte_perm(a1[j].x, a1[j].y, 0x0040),
                                           __byte_perm(a1[j].z, a1[j].w, 0x0040), 0x5410);
                unsigned pk0 = __byte_perm(__byte_perm(a0[j].x, a0[j].y, 0x0040),
                                           __byte_perm(a0[j].z, a0[j].w, 0x0040), 0x5410);
                unsigned r1 = __brev(pk1);     // rev8 of all 4 bytes at once
                unsigned r0 = __brev(pk0);

                // o-cell (0..3) for this lane's quad (compile-time split points)
                const int cA  = g / 72;
                const int thr = (cA + 1) * 72 - g;
                const int qb  = g - cA * 72;

                int q;
                if (thr >= 32) q = qb + lane;
                else           q = (lane < thr) ? (qb + lane) : (qb + lane - 72);
                unsigned gt = __ldg(gwrow + q);

                uint2 twal = s_twal[qw * 288 + g + lane];

                unsigned lt1 = swar_lt(r1, twal.x);
                unsigned lt0 = swar_lt(r0, twal.x);
                unsigned f1  = (lt1 | twal.y) & gt;     // ib * bit1         (bit7-clean)
                unsigned nf0 = (lt0 | twal.y) | gt;     // ~((1-ib)*(1-bit0))
                unsigned p   = (unsigned)__popc(f1 | (~nf0 & HMASK));

                // accumulate into packed counters (cell 0/2 -> lo16, 1/3 -> hi16)
                if (thr >= 32) {
                    if (cA == 0)      c01 += p;
                    else if (cA == 1) c01 += p << 16;
                    else if (cA == 2) c23 += p;
                    else              c23 += p << 16;
                } else {
                    unsigned plo = (lane < thr) ? p : 0u;
                    unsigned phi = p - plo;
                    if (cA == 0)      c01 += plo + (phi << 16);
                    else if (cA == 1) { c01 += plo << 16; c23 += phi; }
                    else              c23 += plo + (phi << 16);
                }
            }
        }

        c01 = __reduce_add_sync(0xffffffffu, c01);
        c23 = __reduce_add_sync(0xffffffffu, c23);

        if (lane == 0) {
            int n = b >> 8, hw = b & 255;
            float* ob = out + (n * OCH + o0) * 256 + hw;
            ob[0]   = (float)(c01 & 0xffffu) + g_bias[o0];
            ob[256] = (float)(c01 >> 16)     + g_bias[o0 + 1];
            ob[512] = (float)(c23 & 0xffffu) + g_bias[o0 + 2];
            ob[768] = (float)(c23 >> 16)     + g_bias[o0 + 3];
        }
    }
}

// ---- launch -----------------------------------------------------------------
extern "C" void kernel_launch(void* const* d_in, const int* in_sizes, int n_in,
                              void* d_out, int out_size) {
    const float* x     = (const float*)d_in[0];   // [8,32,16,16]
    const float* w_bin = (const float*)d_in[1];   // [64,288]
    const float* b_bin = (const float*)d_in[2];   // [64]
    const float* rng   = (const float*)d_in[3];   // [256]
    const int4*  i1    = (const int4*) d_in[4];   // [2048,64,288]
    const int4*  i0    = (const int4*) d_in[5];   // [2048,64,288]
    const int*   brdx  = (const int*)  d_in[6];   // [64]
    float* out = (float*)d_out;                   // [8,64,16,16]

    prep<<<(NB * NQ + 255) / 256, 256>>>(x, b_bin, rng, brdx);

    // main, programmatically overlapped with prep (PDL)
    cudaLaunchConfig_t cfg = {};
    cfg.gridDim  = dim3(GRID, 1, 1);
    cfg.blockDim = dim3(256, 1, 1);
    cudaLaunchAttribute at[1];
    at[0].id = cudaLaunchAttributeProgrammaticStreamSerialization;
    at[0].val.programmaticStreamSerializationAllowed = 1;
    cfg.attrs = at;
    cfg.numAttrs = 1;
    cudaLaunchKernelEx(&cfg, fsu_main, i1, i0, w_bin, out);
}